// round 1
// baseline (speedup 1.0000x reference)
#include <cuda_runtime.h>

// Problem constants
#define Bn 16
#define Jn 16
#define Cn 64
#define Hn 256
#define Wn 256
#define HWn (Hn * Wn)          // 65536
#define SPLIT 4
#define CHUNK (HWn / SPLIT)    // 16384 floats per block
#define NPART (Bn * Jn * SPLIT)

// Scratch for split-K argmax partials (device globals: allocation-free)
__device__ float g_pval[NPART];
__device__ int   g_pidx[NPART];

// ---------------------------------------------------------------------------
// Kernel 1: split-K argmax over heatmap[b,j,:,:]
// grid = B*J*SPLIT blocks, 256 threads. Each block reduces CHUNK floats.
// ---------------------------------------------------------------------------
__global__ __launch_bounds__(256) void argmax_partial_kernel(
    const float* __restrict__ heatmap)
{
    const int blk  = blockIdx.x;
    const int bj   = blk / SPLIT;        // 0..255
    const int s    = blk % SPLIT;
    const int t    = threadIdx.x;

    const float4* __restrict__ src = reinterpret_cast<const float4*>(
        heatmap + (size_t)bj * HWn + (size_t)s * CHUNK);

    // CHUNK/4 = 4096 float4s; 256 threads -> 16 float4 per thread
    float bestv = -3.4028235e38f;
    int   besti = 0x7fffffff;

    #pragma unroll
    for (int it = 0; it < CHUNK / 4 / 256; ++it) {
        const int p = t + it * 256;          // float4 index within chunk
        const float4 v = __ldg(&src[p]);
        const int base = s * CHUNK + p * 4;  // flat index within HW
        // first-occurrence tie-break: strictly-greater replaces; on equal keep
        // smaller index
        if (v.x > bestv || (v.x == bestv && base + 0 < besti)) { bestv = v.x; besti = base + 0; }
        if (v.y > bestv || (v.y == bestv && base + 1 < besti)) { bestv = v.y; besti = base + 1; }
        if (v.z > bestv || (v.z == bestv && base + 2 < besti)) { bestv = v.z; besti = base + 2; }
        if (v.w > bestv || (v.w == bestv && base + 3 < besti)) { bestv = v.w; besti = base + 3; }
    }

    // warp reduce
    #pragma unroll
    for (int off = 16; off > 0; off >>= 1) {
        float ov = __shfl_down_sync(0xffffffff, bestv, off);
        int   oi = __shfl_down_sync(0xffffffff, besti, off);
        if (ov > bestv || (ov == bestv && oi < besti)) { bestv = ov; besti = oi; }
    }

    __shared__ float sv[8];
    __shared__ int   si[8];
    const int wid = t >> 5, lid = t & 31;
    if (lid == 0) { sv[wid] = bestv; si[wid] = besti; }
    __syncthreads();

    if (wid == 0) {
        bestv = (lid < 8) ? sv[lid] : -3.4028235e38f;
        besti = (lid < 8) ? si[lid] : 0x7fffffff;
        #pragma unroll
        for (int off = 4; off > 0; off >>= 1) {
            float ov = __shfl_down_sync(0xffffffff, bestv, off);
            int   oi = __shfl_down_sync(0xffffffff, besti, off);
            if (ov > bestv || (ov == bestv && oi < besti)) { bestv = ov; besti = oi; }
        }
        if (lid == 0) {
            g_pval[bj * SPLIT + s] = bestv;
            g_pidx[bj * SPLIT + s] = besti;
        }
    }
}

// ---------------------------------------------------------------------------
// Kernel 2: finalize argmax across splits, gather pred, MSE, write out[B]
// grid = B blocks, 256 threads.
// ---------------------------------------------------------------------------
__global__ __launch_bounds__(256) void loss_kernel(
    const float* __restrict__ pred,
    const float* __restrict__ gt,
    float* __restrict__ out)
{
    const int b = blockIdx.x;
    const int t = threadIdx.x;

    __shared__ int s_idx[Jn];

    if (t < Jn) {
        const int bj = b * Jn + t;
        float bv = -3.4028235e38f;
        int   bi = 0x7fffffff;
        #pragma unroll
        for (int s = 0; s < SPLIT; ++s) {
            float v = g_pval[bj * SPLIT + s];
            int   i = g_pidx[bj * SPLIT + s];
            if (v > bv || (v == bv && i < bi)) { bv = v; bi = i; }
        }
        s_idx[t] = bi;
    }
    __syncthreads();

    // J*C = 1024 elements, 256 threads -> 4 each
    float acc = 0.0f;
    #pragma unroll
    for (int it = 0; it < (Jn * Cn) / 256; ++it) {
        const int e = t + it * 256;
        const int j = e >> 6;        // /64
        const int c = e & 63;        // %64
        const int idx = s_idx[j];
        const float p = __ldg(&pred[((size_t)b * Cn + c) * HWn + idx]);
        const float g = __ldg(&gt[((size_t)b * Jn + j) * Cn + c]);
        const float d = p - g;
        acc += d * d;
    }

    // block reduce sum
    #pragma unroll
    for (int off = 16; off > 0; off >>= 1)
        acc += __shfl_down_sync(0xffffffff, acc, off);

    __shared__ float ss[8];
    const int wid = t >> 5, lid = t & 31;
    if (lid == 0) ss[wid] = acc;
    __syncthreads();
    if (wid == 0) {
        acc = (lid < 8) ? ss[lid] : 0.0f;
        #pragma unroll
        for (int off = 4; off > 0; off >>= 1)
            acc += __shfl_down_sync(0xffffffff, acc, off);
        if (lid == 0) out[b] = acc * (1.0f / (Jn * Cn));
    }
}

extern "C" void kernel_launch(void* const* d_in, const int* in_sizes, int n_in,
                              void* d_out, int out_size)
{
    const float* pred    = (const float*)d_in[0];   // [B,C,H,W]
    const float* gt      = (const float*)d_in[1];   // [B,J,C]
    const float* heatmap = (const float*)d_in[2];   // [B,J,H,W]
    float* out = (float*)d_out;                     // [B]

    argmax_partial_kernel<<<NPART, 256>>>(heatmap);
    loss_kernel<<<Bn, 256>>>(pred, gt, out);
}

// round 2
// speedup vs baseline: 1.0225x; 1.0225x over previous
#include <cuda_runtime.h>

// Problem constants
#define Bn 16
#define Jn 16
#define Cn 64
#define Hn 256
#define Wn 256
#define HWn (Hn * Wn)          // 65536
#define SPLIT 4
#define CHUNK (HWn / SPLIT)    // 16384 floats per split-block
#define NPART (Bn * Jn * SPLIT)
#define BLKS_PER_B (Jn * SPLIT)   // 64 blocks contribute to each batch

// Scratch (device globals: allocation-free). g_count is zero-initialized at
// module load; each finalizer resets its slot to 0 so graph replays are
// deterministic.
__device__ float g_pval[NPART];
__device__ int   g_pidx[NPART];
__device__ int   g_count[Bn];

// ---------------------------------------------------------------------------
// Fused kernel: split-K argmax over heatmap + last-block-per-batch finalize
// grid = B*J*SPLIT = 1024 blocks, 256 threads.
// ---------------------------------------------------------------------------
__global__ __launch_bounds__(256) void fused_labelloss_kernel(
    const float* __restrict__ heatmap,
    const float* __restrict__ pred,
    const float* __restrict__ gt,
    float* __restrict__ out)
{
    const int blk = blockIdx.x;
    const int bj  = blk / SPLIT;         // 0..255  (= b*Jn + j)
    const int s   = blk % SPLIT;
    const int b   = bj / Jn;
    const int t   = threadIdx.x;

    // ---------------- Phase 1: partial argmax over this chunk ----------------
    const float4* __restrict__ src = reinterpret_cast<const float4*>(
        heatmap + (size_t)bj * HWn + (size_t)s * CHUNK);

    float bestv = -3.4028235e38f;
    int   besti = 0x7fffffff;

    #pragma unroll
    for (int it = 0; it < CHUNK / 4 / 256; ++it) {
        const int p = t + it * 256;          // float4 index within chunk
        const float4 v = __ldg(&src[p]);
        const int base = s * CHUNK + p * 4;  // flat index within HW
        if (v.x > bestv || (v.x == bestv && base + 0 < besti)) { bestv = v.x; besti = base + 0; }
        if (v.y > bestv || (v.y == bestv && base + 1 < besti)) { bestv = v.y; besti = base + 1; }
        if (v.z > bestv || (v.z == bestv && base + 2 < besti)) { bestv = v.z; besti = base + 2; }
        if (v.w > bestv || (v.w == bestv && base + 3 < besti)) { bestv = v.w; besti = base + 3; }
    }

    // warp reduce
    #pragma unroll
    for (int off = 16; off > 0; off >>= 1) {
        float ov = __shfl_down_sync(0xffffffff, bestv, off);
        int   oi = __shfl_down_sync(0xffffffff, besti, off);
        if (ov > bestv || (ov == bestv && oi < besti)) { bestv = ov; besti = oi; }
    }

    __shared__ float sv[8];
    __shared__ int   si[8];
    __shared__ int   s_last;     // broadcast: is this the finalizer block?
    const int wid = t >> 5, lid = t & 31;
    if (lid == 0) { sv[wid] = bestv; si[wid] = besti; }
    __syncthreads();

    if (t < 32) {
        bestv = (lid < 8) ? sv[lid] : -3.4028235e38f;
        besti = (lid < 8) ? si[lid] : 0x7fffffff;
        #pragma unroll
        for (int off = 4; off > 0; off >>= 1) {
            float ov = __shfl_down_sync(0xffffffff, bestv, off);
            int   oi = __shfl_down_sync(0xffffffff, besti, off);
            if (ov > bestv || (ov == bestv && oi < besti)) { bestv = ov; besti = oi; }
        }
        if (lid == 0) {
            g_pval[bj * SPLIT + s] = bestv;
            g_pidx[bj * SPLIT + s] = besti;
            __threadfence();  // make partials visible before signaling
            const int prev = atomicAdd(&g_count[b], 1);
            s_last = (prev == BLKS_PER_B - 1) ? 1 : 0;
        }
    }
    __syncthreads();

    if (!s_last) return;

    // ------------- Phase 2: finalizer for batch b (64th arriver) -------------
    __shared__ int s_idx[Jn];

    if (t < Jn) {
        const int base = (b * Jn + t) * SPLIT;
        float bv = -3.4028235e38f;
        int   bi = 0x7fffffff;
        #pragma unroll
        for (int k = 0; k < SPLIT; ++k) {
            // bypass L1: partials were written by other SMs
            const float v = __ldcg(&g_pval[base + k]);
            const int   i = __ldcg(&g_pidx[base + k]);
            if (v > bv || (v == bv && i < bi)) { bv = v; bi = i; }
        }
        s_idx[t] = bi;
    }
    __syncthreads();

    // J*C = 1024 gathered elements, 256 threads -> 4 each
    float acc = 0.0f;
    #pragma unroll
    for (int it = 0; it < (Jn * Cn) / 256; ++it) {
        const int e = t + it * 256;
        const int j = e >> 6;        // /64
        const int c = e & 63;        // %64
        const int idx = s_idx[j];
        const float p = __ldg(&pred[((size_t)b * Cn + c) * HWn + idx]);
        const float g = __ldg(&gt[((size_t)b * Jn + j) * Cn + c]);
        const float d = p - g;
        acc += d * d;
    }

    // block reduce sum
    #pragma unroll
    for (int off = 16; off > 0; off >>= 1)
        acc += __shfl_down_sync(0xffffffff, acc, off);

    __shared__ float ss[8];
    if (lid == 0) ss[wid] = acc;
    __syncthreads();
    if (t < 32) {
        acc = (lid < 8) ? ss[lid] : 0.0f;
        #pragma unroll
        for (int off = 4; off > 0; off >>= 1)
            acc += __shfl_down_sync(0xffffffff, acc, off);
        if (lid == 0) {
            out[b] = acc * (1.0f / (Jn * Cn));
            g_count[b] = 0;   // reset for next graph replay (deterministic)
        }
    }
}

extern "C" void kernel_launch(void* const* d_in, const int* in_sizes, int n_in,
                              void* d_out, int out_size)
{
    const float* pred    = (const float*)d_in[0];   // [B,C,H,W]
    const float* gt      = (const float*)d_in[1];   // [B,J,C]
    const float* heatmap = (const float*)d_in[2];   // [B,J,H,W]
    float* out = (float*)d_out;                     // [B]

    fused_labelloss_kernel<<<NPART, 256>>>(heatmap, pred, gt, out);
}